// round 10
// baseline (speedup 1.0000x reference)
#include <cuda_runtime.h>
#include <cuda_fp16.h>
#include <cstdint>
#include <math_constants.h>

#define NT     65536
#define DIM    256
#define NE     1024
#define MCTA   64
#define MQ     32            // capture window in q-units (3.05e-5 each)
#define CCAP   12            // per (row, N-half)

// ---------------- smem layout (bytes) ----------------
#define SA16  0              // z tile fp16: 64 rows x 136 words (pair-permuted)  34816
#define SBB   34816          // 2 B chunk buffers x 20480 (k64 chunks)            40960
#define SE2   75776          // e2 all 1024 f32                                    4096
#define SZ2   79872          // row norms f32 [64]                                  256
#define SRK   80128          // packed row min key [64] int                         256
#define SCNT  80384          // cand counts [64][2] int                             512
#define SCL   80896          // cand lists [64][2][CCAP] int                       6144
#define SBI   87040          // best index [64] int                                 256
#define SRED  87296          // loss reduction [256] double                        2048
#define SMEM_TOTAL 89344     // ~87 KB -> 2 CTAs/SM

#define A_STRIDE_W   136
#define B_STRIDE_W   40      // 32 data + 8 pad words per code row in chunk
#define BBUF_BYTES   20480

__device__ double g_loss_acc;
__device__ float  g_e2[NE];
// pair-permuted fp16 codebook: per code, within each 16-half group G:
// new half[4q..4q+3] = old halves (2q, 2q+1, 2q+8, 2q+9)
__device__ __align__(16) __half g_cb16[NE * DIM];

#define CP16(dst, src) asm volatile("cp.async.cg.shared.global [%0], [%1], 16;" :: "r"(dst), "l"(src) : "memory")
#define CP_COMMIT()    asm volatile("cp.async.commit_group;" ::: "memory")
#define CP_WAIT1()     asm volatile("cp.async.wait_group 1;" ::: "memory")

__device__ __forceinline__ uint32_t smem_u32(const void* p) {
    uint32_t a;
    asm("{ .reg .u64 t; cvta.to.shared.u64 t, %1; cvt.u32.u64 %0, t; }" : "=r"(a) : "l"(p));
    return a;
}

__device__ __forceinline__ void mma16816(float& c0, float& c1, float& c2, float& c3,
                                         uint32_t a0, uint32_t a1, uint32_t a2, uint32_t a3,
                                         uint32_t b0, uint32_t b1) {
    asm volatile("mma.sync.aligned.m16n8k16.row.col.f32.f16.f16.f32 "
                 "{%0,%1,%2,%3},{%4,%5,%6,%7},{%8,%9},{%0,%1,%2,%3};"
                 : "+f"(c0), "+f"(c1), "+f"(c2), "+f"(c3)
                 : "r"(a0), "r"(a1), "r"(a2), "r"(a3), "r"(b0), "r"(b1));
}

// ---------------- prep: e2 (fp64) + cb->fp16 pair-permuted + zero loss ----------------
__global__ void vq_prep_kernel(const float* __restrict__ cb) {
    int tid = threadIdx.x, lane = tid & 31;
    if (blockIdx.x == 0 && tid == 0) g_loss_acc = 0.0;
    int gw = blockIdx.x * 8 + (tid >> 5);
    #pragma unroll
    for (int i = 0; i < 4; i++) {
        int c = gw * 4 + i;
        const float* row = cb + (size_t)c * DIM;
        double s = 0.0;
        #pragma unroll
        for (int j = 0; j < 8; j++) { double v = (double)row[lane + 32 * j]; s += v * v; }
        #pragma unroll
        for (int o = 16; o; o >>= 1) s += __shfl_xor_sync(0xffffffffu, s, o);
        if (lane == 0) g_e2[c] = (float)s;
    }
    uint32_t* out16 = (uint32_t*)g_cb16;
    int base = blockIdx.x * 256 + tid;
    #pragma unroll
    for (int i = 0; i < 16; i++) {
        int w = base + i * 8192;
        int n = w >> 7, m = w & 127;
        int G = m >> 3, p = m & 7;
        int q = p >> 1, hi = p & 1;
        int k0 = G * 16 + (hi ? (2 * q + 8) : (2 * q));
        __half2 h = __floats2half2_rn(cb[(size_t)n * DIM + k0], cb[(size_t)n * DIM + k0 + 1]);
        out16[w] = *(uint32_t*)&h;
    }
}

// ---------------- main ----------------
__global__ __launch_bounds__(256, 2) void vq_main_kernel(
    const float* __restrict__ z,
    const float* __restrict__ cb,
    float* __restrict__ out)
{
    extern __shared__ char smem[];
    const uint32_t sbu = smem_u32(smem);
    uint32_t* a16w  = (uint32_t*)(smem + SA16);
    float*    e2s   = (float*)(smem + SE2);
    float*    z2s   = (float*)(smem + SZ2);
    int*      rkey  = (int*)(smem + SRK);
    int*      cnts  = (int*)(smem + SCNT);
    int*      cl    = (int*)(smem + SCL);
    int*      bi_s  = (int*)(smem + SBI);

    const int tid  = threadIdx.x;
    const int wid  = tid >> 5;
    const int lane = tid & 31;
    const int q    = lane & 3;
    const int lq   = lane >> 2;
    const int m0   = blockIdx.x * MCTA;
    const int rw   = (wid & 3) * 16;     // warp row base (4 warps in M)
    const int nb2  = (wid >> 2);         // warp col half of ntile (2 warps in N)

    // ---- stage A fp16 pair-permuted, e2 table, init ----
    #pragma unroll
    for (int i = 0; i < 16; i++) {
        int s = i * 256 + tid;
        int row = s >> 6, c4 = s & 63;
        float4 v = *(const float4*)(z + (size_t)(m0 + row) * DIM + c4 * 4);
        __half2 h0 = __floats2half2_rn(v.x, v.y);
        __half2 h1 = __floats2half2_rn(v.z, v.w);
        int w0 = 2 * c4, w1 = w0 + 1;
        int g0 = w0 >> 3, p0 = w0 & 7;
        int n0 = g0 * 8 + (p0 < 4 ? 2 * p0 : 2 * (p0 - 4) + 1);
        int g1 = w1 >> 3, p1 = w1 & 7;
        int n1 = g1 * 8 + (p1 < 4 ? 2 * p1 : 2 * (p1 - 4) + 1);
        a16w[row * A_STRIDE_W + n0] = *(uint32_t*)&h0;
        a16w[row * A_STRIDE_W + n1] = *(uint32_t*)&h1;
    }
    #pragma unroll
    for (int i = 0; i < 4; i++) e2s[i * 256 + tid] = g_e2[i * 256 + tid];
    if (tid < MCTA) rkey[tid] = 0x7fffffff;
    if (tid < 2 * MCTA) cnts[tid] = 0;

    // ---- row norms: warp-parallel fp64 (warp w owns rows 8w..8w+7) ----
    #pragma unroll
    for (int rr = 0; rr < 8; rr++) {
        int r = wid * 8 + rr;
        const float* zr = z + (size_t)(m0 + r) * DIM;
        double s = 0.0;
        #pragma unroll
        for (int i = 0; i < 8; i++) { double v = (double)zr[lane + 32 * i]; s += v * v; }
        #pragma unroll
        for (int o = 16; o; o >>= 1) s += __shfl_xor_sync(0xffffffffu, s, o);
        if (lane == 0) z2s[r] = (float)s;
    }
    __syncthreads();

    // ---- B chunk loader: chunk c -> ntile c>>2, k64-chunk c&3, buffer c&1 ----
    auto load_chunk = [&](int c) {
        int nt = c >> 2, kc = c & 3;
        const char* src0 = (const char*)g_cb16 + (size_t)nt * 128 * 512 + kc * 128;
        uint32_t bbase = sbu + SBB + (c & 1) * BBUF_BYTES;
        #pragma unroll
        for (int i = 0; i < 4; i++) {
            int s = i * 256 + tid;
            int n = s >> 3, seg = s & 7;
            CP16(bbase + n * 160 + seg * 16, src0 + (size_t)n * 512 + seg * 16);
        }
    };
    load_chunk(0); CP_COMMIT();
    load_chunk(1); CP_COMMIT();

    float acc[8][4];
    #pragma unroll
    for (int j = 0; j < 8; j++)
        #pragma unroll
        for (int e = 0; e < 4; e++) acc[j][e] = 0.0f;

    const int r0 = rw + lq;
    for (int c = 0; c < 32; c++) {
        const int nt = c >> 2, kc = c & 3;
        CP_WAIT1();
        __syncthreads();

        const uint32_t* Bw = (const uint32_t*)(smem + SBB + (c & 1) * BBUF_BYTES);
        #pragma unroll
        for (int g = 0; g < 4; g++) {
            const int aw = (kc * 4 + g) * 8 + 2 * q;
            uint2 A0 = *(const uint2*)(a16w + r0 * A_STRIDE_W + aw);
            uint2 A1 = *(const uint2*)(a16w + (r0 + 8) * A_STRIDE_W + aw);
            #pragma unroll
            for (int j = 0; j < 8; j++) {
                int nl = nb2 * 64 + 8 * j + lq;
                uint2 B0 = *(const uint2*)(Bw + nl * B_STRIDE_W + g * 8 + 2 * q);
                mma16816(acc[j][0], acc[j][1], acc[j][2], acc[j][3],
                         A0.x, A1.x, A0.y, A1.y, B0.x, B0.y);
            }
        }

        if (kc == 3) {
            // q16 = round((e2 - 2*dot)*2^15) biased by 32768; key = qb<<10 | col
            int thr0 = (rkey[r0] >> 10) + MQ;           // stale-safe (>= final)
            int thr1 = (rkey[r0 + 8] >> 10) + MQ;
            int key0 = 0x7fffffff, key1 = 0x7fffffff;
            #pragma unroll
            for (int j = 0; j < 8; j++) {
                int col0 = nt * 128 + nb2 * 64 + 8 * j + 2 * q;
                float e20 = e2s[col0], e21 = e2s[col0 + 1];
                #pragma unroll
                for (int h = 0; h < 2; h++) {
                    float s0 = e20 - 2.0f * acc[j][h * 2 + 0];
                    float s1 = e21 - 2.0f * acc[j][h * 2 + 1];
                    int qb0 = max(1, min(65535, __float2int_rn(s0 * 32768.0f) + 32768));
                    int qb1 = max(1, min(65535, __float2int_rn(s1 * 32768.0f) + 32768));
                    int& key = h ? key1 : key0;
                    int  thr = h ? thr1 : thr0;
                    int  rr  = r0 + 8 * h;
                    int k0p = (qb0 << 10) | col0;
                    if (k0p < key) key = k0p;
                    if (qb0 <= min(thr, (key >> 10) + MQ)) {
                        int p = atomicAdd(&cnts[rr * 2 + nb2], 1);
                        if (p < CCAP) cl[(rr * 2 + nb2) * CCAP + p] = col0;
                    }
                    int k1p = (qb1 << 10) | (col0 + 1);
                    if (k1p < key) key = k1p;
                    if (qb1 <= min(thr, (key >> 10) + MQ)) {
                        int p = atomicAdd(&cnts[rr * 2 + nb2], 1);
                        if (p < CCAP) cl[(rr * 2 + nb2) * CCAP + p] = col0 + 1;
                    }
                    acc[j][h * 2 + 0] = 0.0f;
                    acc[j][h * 2 + 1] = 0.0f;
                }
            }
            atomicMin(&rkey[r0], key0);
            atomicMin(&rkey[r0 + 8], key1);
        }

        __syncthreads();
        if (c + 2 < 32) load_chunk(c + 2);
        CP_COMMIT();
    }
    __syncthreads();

    // ---- exact fp32 rescue (R1's serial FMA order) ----
    if (tid < MCTA) {
        const int r = tid;
        const float z2f = z2s[r];
        const float* zr = z + (size_t)(m0 + r) * DIM;
        auto exact_dd = [&](int cidx) -> float {
            const float* cr = cb + (size_t)cidx * DIM;
            float a = 0.0f;
            #pragma unroll 8
            for (int k = 0; k < DIM; k++)
                a = fmaf(__ldg(zr + k), __ldg(cr + k), a);
            return (z2f - 2.0f * a) + e2s[cidx];
        };
        int cn0 = cnts[r * 2], cn1 = cnts[r * 2 + 1];
        float best = CUDART_INF_F; int bi = 0x7fffffff;
        if (cn0 <= CCAP && cn1 <= CCAP) {
            // guaranteed candidate from the packed min key
            int am = rkey[r] & 1023;
            best = exact_dd(am); bi = am;
            for (int hh = 0; hh < 2; hh++) {
                int cn = hh ? cn1 : cn0;
                for (int p = 0; p < cn; p++) {
                    int cidx = cl[(r * 2 + hh) * CCAP + p];
                    if (cidx == am) continue;
                    float d2 = exact_dd(cidx);
                    if (d2 < best || (d2 == best && cidx < bi)) { best = d2; bi = cidx; }
                }
            }
        } else {
            // provably-safe fallback: full exact scan (expected ~never)
            for (int cidx = 0; cidx < NE; cidx++) {
                float d2 = exact_dd(cidx);
                if (d2 < best || (d2 == best && cidx < bi)) { best = d2; bi = cidx; }
            }
        }
        bi_s[r] = bi;
    }
    __syncthreads();

    // ---- epilogue: z_q_st (exact ST rounding), indices, loss ----
    float lacc = 0.0f;
    #pragma unroll 4
    for (int it = 0; it < MCTA; it++) {
        float zv = z[(size_t)(m0 + it) * DIM + tid];
        float e  = __ldg(cb + (size_t)bi_s[it] * DIM + tid);
        float dq = e - zv;                  // fl(z_q - z)
        float o  = zv + dq;                 // fl(z + fl(z_q - z))
        out[(size_t)(m0 + it) * DIM + tid] = o;
        lacc = fmaf(dq, dq, lacc);
    }
    if (tid < MCTA)
        out[(size_t)NT * DIM + 1 + m0 + tid] = (float)bi_s[tid];

    double* red = (double*)(smem + SRED);
    red[tid] = (double)lacc;
    __syncthreads();
    #pragma unroll
    for (int s = 128; s > 0; s >>= 1) {
        if (tid < s) red[tid] += red[tid + s];
        __syncthreads();
    }
    if (tid == 0) atomicAdd(&g_loss_acc, red[0]);
}

__global__ void vq_loss_kernel(float* __restrict__ out) {
    out[(size_t)NT * DIM] = (float)(1.25 * g_loss_acc / ((double)NT * (double)DIM));
}

// ---------------------------------------------------------------------------
extern "C" void kernel_launch(void* const* d_in, const int* in_sizes, int n_in,
                              void* d_out, int out_size) {
    const float *z, *cb;
    if (in_sizes[0] == NT * DIM) { z = (const float*)d_in[0]; cb = (const float*)d_in[1]; }
    else                         { z = (const float*)d_in[1]; cb = (const float*)d_in[0]; }
    float* out = (float*)d_out;

    cudaFuncSetAttribute(vq_main_kernel,
                         cudaFuncAttributeMaxDynamicSharedMemorySize, SMEM_TOTAL);

    vq_prep_kernel<<<32, 256>>>(cb);
    vq_main_kernel<<<NT / MCTA, 256, SMEM_TOTAL>>>(z, cb, out);
    vq_loss_kernel<<<1, 1>>>(out);
}

// round 11
// speedup vs baseline: 155.3721x; 155.3721x over previous
#include <cuda_runtime.h>
#include <cstdint>
#include <math_constants.h>

#define NT     65536
#define DIM    256
#define NE     1024
#define MCTA   64
#define CCAP   48

// ---------------- smem layout (bytes) ----------------
#define SA8   0              // z tile int8: 64 rows x 72 words (pair-permuted)   18432
#define SBB   18432          // 2 B chunk buffers x 10240 (k64 chunks)            20480
#define SQD   38912          // qd: 64 rows x 516 u32 words (s16 pairs)          132096
#define SE2   171008         // e2 all 1024 f32                                    4096
#define SZ2   175104         // row norms f32 [64]                                  256
#define SINV  175360         // per-row inv dot scale f32 [64]                      256
#define SWQ   175616         // per-row capture window (q units) [64] int           256
#define SSZ   175872         // per-row z quant scale f32 [64]                      256
#define SCN   176128         // cand count [64] int                                 256
#define SMINQ 176384         // min q per row [64] int                              256
#define SBI   176640         // best index [64] int                                 256
#define SCL   176896         // cand list [64][CCAP] int                          12288
#define SRED  189184         // loss reduction [256] double                        2048
#define SMEM_TOTAL 191232

#define A8_STRIDE_W  72      // 64 data words + 8 pad per row
#define B_STRIDE_W   20      // 16 data + 4 pad words per code row in chunk
#define BBUF_BYTES   10240
#define QD_STRIDE_W  516

__device__ double g_loss_acc;
__device__ float  g_e2[NE];
__device__ unsigned g_cbmax_bits;   // max |c| (fp32 bits, positive-monotone)
__device__ unsigned g_scmax_bits;   // max over codes of sum|c|
// pair-permuted int8 codebook: per code 256 bytes = 8 groups of 32 k;
// within each group's 8 words, stored[2q]=orig[q], stored[2q+1]=orig[q+4]
__device__ __align__(16) signed char g_cb8[NE * DIM];

#define CP16(dst, src) asm volatile("cp.async.cg.shared.global [%0], [%1], 16;" :: "r"(dst), "l"(src) : "memory")
#define CP_COMMIT()    asm volatile("cp.async.commit_group;" ::: "memory")
#define CP_WAIT1()     asm volatile("cp.async.wait_group 1;" ::: "memory")

__device__ __forceinline__ uint32_t smem_u32(const void* p) {
    uint32_t a;
    asm("{ .reg .u64 t; cvta.to.shared.u64 t, %1; cvt.u32.u64 %0, t; }" : "=r"(a) : "l"(p));
    return a;
}

__device__ __forceinline__ void mma_s8(int& c0, int& c1, int& c2, int& c3,
                                       uint32_t a0, uint32_t a1, uint32_t a2, uint32_t a3,
                                       uint32_t b0, uint32_t b1) {
    asm volatile("mma.sync.aligned.m16n8k32.row.col.s32.s8.s8.s32 "
                 "{%0,%1,%2,%3},{%4,%5,%6,%7},{%8,%9},{%0,%1,%2,%3};"
                 : "+r"(c0), "+r"(c1), "+r"(c2), "+r"(c3)
                 : "r"(a0), "r"(a1), "r"(a2), "r"(a3), "r"(b0), "r"(b1));
}

__device__ __forceinline__ int quant8(float v, float s) {
    int x = __float2int_rn(v * s);
    return max(-127, min(127, x));
}

// ---------------- prep1: e2 (fp64) + cb stats + zero loss ----------------
__global__ void vq_prep1_kernel(const float* __restrict__ cb) {
    int tid = threadIdx.x, lane = tid & 31;
    if (blockIdx.x == 0 && tid == 0) g_loss_acc = 0.0;
    int gw = blockIdx.x * 8 + (tid >> 5);
    #pragma unroll
    for (int i = 0; i < 4; i++) {
        int c = gw * 4 + i;
        const float* row = cb + (size_t)c * DIM;
        double s = 0.0; float sa = 0.0f, mx = 0.0f;
        #pragma unroll
        for (int j = 0; j < 8; j++) {
            float v = row[lane + 32 * j];
            s += (double)v * (double)v;
            sa += fabsf(v);
            mx = fmaxf(mx, fabsf(v));
        }
        #pragma unroll
        for (int o = 16; o; o >>= 1) {
            s  += __shfl_xor_sync(0xffffffffu, s, o);
            sa += __shfl_xor_sync(0xffffffffu, sa, o);
            mx = fmaxf(mx, __shfl_xor_sync(0xffffffffu, mx, o));
        }
        if (lane == 0) {
            g_e2[c] = (float)s;
            atomicMax(&g_cbmax_bits, __float_as_uint(mx));
            atomicMax(&g_scmax_bits, __float_as_uint(sa));
        }
    }
}

// ---------------- prep2: quantize codebook int8 pair-permuted ----------------
__global__ void vq_prep2_kernel(const float* __restrict__ cb) {
    float cbmax = __uint_as_float(g_cbmax_bits);
    float sc = (cbmax > 0.0f) ? 126.0f / cbmax : 1.0f;
    uint32_t* out8 = (uint32_t*)g_cb8;
    int base = blockIdx.x * 256 + threadIdx.x;
    #pragma unroll
    for (int i = 0; i < 8; i++) {
        int w = base + i * 8192;           // output word (4 int8)
        int n = w >> 6, m = w & 63;        // code, word-in-row
        int G = m >> 3, p = m & 7;
        int o = (p & 1) ? ((p >> 1) + 4) : (p >> 1);
        int k0 = G * 32 + o * 4;
        const float* src = cb + (size_t)n * DIM + k0;
        int b0 = quant8(src[0], sc), b1 = quant8(src[1], sc);
        int b2 = quant8(src[2], sc), b3 = quant8(src[3], sc);
        out8[w] = (uint32_t)(b0 & 0xff) | ((uint32_t)(b1 & 0xff) << 8)
                | ((uint32_t)(b2 & 0xff) << 16) | ((uint32_t)(b3 & 0xff) << 24);
    }
}

// ---------------- main ----------------
__global__ __launch_bounds__(256) void vq_main_kernel(
    const float* __restrict__ z,
    const float* __restrict__ cb,
    float* __restrict__ out)
{
    extern __shared__ char smem[];
    const uint32_t sbu = smem_u32(smem);
    uint32_t* a8w   = (uint32_t*)(smem + SA8);
    uint32_t* qd    = (uint32_t*)(smem + SQD);
    float*    e2s   = (float*)(smem + SE2);
    float*    z2s   = (float*)(smem + SZ2);
    float*    invs  = (float*)(smem + SINV);
    int*      wqs   = (int*)(smem + SWQ);
    float*    szs   = (float*)(smem + SSZ);
    int*      ccnt  = (int*)(smem + SCN);
    int*      minqs = (int*)(smem + SMINQ);
    int*      bi_s  = (int*)(smem + SBI);
    int*      clist = (int*)(smem + SCL);

    const int tid  = threadIdx.x;
    const int wid  = tid >> 5;
    const int lane = tid & 31;
    const int q    = lane & 3;
    const int lq   = lane >> 2;
    const int m0   = blockIdx.x * MCTA;
    const int rw   = (wid & 3) * 16;
    const int nb2  = (wid >> 2);

    const float cbmax = __uint_as_float(g_cbmax_bits);
    const float scmax = __uint_as_float(g_scmax_bits);
    const float sc  = (cbmax > 0.0f) ? 126.0f / cbmax : 1.0f;
    const float dcq = 0.5f / sc;

    // ---- e2 table ----
    #pragma unroll
    for (int i = 0; i < 4; i++) e2s[i * 256 + tid] = g_e2[i * 256 + tid];
    if (tid < MCTA) ccnt[tid] = 0;

    // ---- per-row stats: z2 (fp64), sum|z|, max|z| -> scale, inv, window ----
    #pragma unroll
    for (int rr = 0; rr < 8; rr++) {
        int r = wid * 8 + rr;
        const float* zr = z + (size_t)(m0 + r) * DIM;
        double s = 0.0; float sa = 0.0f, mx = 0.0f;
        #pragma unroll
        for (int i = 0; i < 8; i++) {
            float v = zr[lane + 32 * i];
            s += (double)v * (double)v;
            sa += fabsf(v);
            mx = fmaxf(mx, fabsf(v));
        }
        #pragma unroll
        for (int o = 16; o; o >>= 1) {
            s  += __shfl_xor_sync(0xffffffffu, s, o);
            sa += __shfl_xor_sync(0xffffffffu, sa, o);
            mx = fmaxf(mx, __shfl_xor_sync(0xffffffffu, mx, o));
        }
        if (lane == 0) {
            float sz = (mx > 0.0f) ? 126.0f / mx : 1.0f;
            float dzr = 0.5f / sz;
            float E = dzr * scmax + dcq * sa + 256.0f * dzr * dcq;  // hard dot-err bound
            z2s[r]  = (float)s;
            szs[r]  = sz;
            invs[r] = 1.0f / (sz * sc);
            wqs[r]  = (int)(4.0f * E * 32768.0f) + 8;
        }
    }
    __syncthreads();

    // ---- stage A int8 pair-permuted ----
    #pragma unroll
    for (int i = 0; i < 16; i++) {
        int s = i * 256 + tid;
        int row = s >> 6, ow = s & 63;
        int G = ow >> 3, o = ow & 7;
        int k0 = G * 32 + o * 4;
        float sz = szs[row];
        const float* src = z + (size_t)(m0 + row) * DIM + k0;
        int b0 = quant8(src[0], sz), b1 = quant8(src[1], sz);
        int b2 = quant8(src[2], sz), b3 = quant8(src[3], sz);
        int dw = (o < 4) ? 2 * o : 2 * (o - 4) + 1;
        a8w[row * A8_STRIDE_W + G * 8 + dw] =
            (uint32_t)(b0 & 0xff) | ((uint32_t)(b1 & 0xff) << 8)
          | ((uint32_t)(b2 & 0xff) << 16) | ((uint32_t)(b3 & 0xff) << 24);
    }
    __syncthreads();

    // ---- B chunk loader: chunk c -> ntile c>>2, k64-chunk c&3, buffer c&1 ----
    auto load_chunk = [&](int c) {
        int nt = c >> 2, kc = c & 3;
        const char* src0 = (const char*)g_cb8 + (size_t)nt * 128 * 256 + kc * 64;
        uint32_t bbase = sbu + SBB + (c & 1) * BBUF_BYTES;
        #pragma unroll
        for (int i = 0; i < 2; i++) {
            int s = i * 256 + tid;           // 512 16B segs
            int n = s >> 2, seg = s & 3;
            CP16(bbase + n * 80 + seg * 16, src0 + (size_t)n * 256 + seg * 16);
        }
    };
    load_chunk(0); CP_COMMIT();
    load_chunk(1); CP_COMMIT();

    int acc[8][4];
    #pragma unroll
    for (int j = 0; j < 8; j++)
        #pragma unroll
        for (int e = 0; e < 4; e++) acc[j][e] = 0;

    const int r0 = rw + lq;
    const float inv0 = invs[r0], inv1 = invs[r0 + 8];

    for (int c = 0; c < 32; c++) {
        const int nt = c >> 2, kc = c & 3;
        CP_WAIT1();
        __syncthreads();

        const uint32_t* Bw = (const uint32_t*)(smem + SBB + (c & 1) * BBUF_BYTES);
        #pragma unroll
        for (int g = 0; g < 2; g++) {
            const int aw = (kc * 2 + g) * 8 + 2 * q;
            uint2 A0 = *(const uint2*)(a8w + r0 * A8_STRIDE_W + aw);
            uint2 A1 = *(const uint2*)(a8w + (r0 + 8) * A8_STRIDE_W + aw);
            #pragma unroll
            for (int j = 0; j < 8; j++) {
                int nl = nb2 * 64 + 8 * j + lq;
                uint2 B0 = *(const uint2*)(Bw + nl * B_STRIDE_W + g * 8 + 2 * q);
                mma_s8(acc[j][0], acc[j][1], acc[j][2], acc[j][3],
                       A0.x, A1.x, A0.y, A1.y, B0.x, B0.y);
            }
        }

        if (kc == 3) {
            // q16 = round((e2 - 2*isum*inv) * 2^15)
            #pragma unroll
            for (int j = 0; j < 8; j++) {
                int col0 = nt * 128 + nb2 * 64 + 8 * j + 2 * q;
                float e20 = e2s[col0], e21 = e2s[col0 + 1];
                int wIdx = (col0 >> 1);
                #pragma unroll
                for (int h = 0; h < 2; h++) {
                    float inv = h ? inv1 : inv0;
                    float s0 = e20 - 2.0f * ((float)acc[j][h * 2 + 0] * inv);
                    float s1 = e21 - 2.0f * ((float)acc[j][h * 2 + 1] * inv);
                    int q0 = max(-32767, min(32767, __float2int_rn(s0 * 32768.0f)));
                    int q1 = max(-32767, min(32767, __float2int_rn(s1 * 32768.0f)));
                    qd[(r0 + 8 * h) * QD_STRIDE_W + wIdx] =
                        ((uint32_t)(q1 & 0xffff) << 16) | (uint32_t)(q0 & 0xffff);
                    acc[j][h * 2 + 0] = 0;
                    acc[j][h * 2 + 1] = 0;
                }
            }
        }

        __syncthreads();
        if (c + 2 < 32) load_chunk(c + 2);
        CP_COMMIT();
    }
    __syncthreads();

    // ---- per-row FINAL min + capture vs hard per-row window ----
    for (int rr = 0; rr < 8; rr++) {
        int r = wid * 8 + rr;
        const uint32_t* row = qd + r * QD_STRIDE_W;
        uint32_t v[16];
        int mn = 0x7fffffff;
        #pragma unroll
        for (int i = 0; i < 16; i++) {
            v[i] = row[lane + 32 * i];
            int a = (int)(short)(v[i] & 0xffff);
            int b = (int)(short)(v[i] >> 16);
            mn = min(mn, min(a, b));
        }
        #pragma unroll
        for (int o = 16; o; o >>= 1) mn = min(mn, __shfl_xor_sync(0xffffffffu, mn, o));
        int thr = mn + wqs[r];
        #pragma unroll
        for (int i = 0; i < 16; i++) {
            int a = (int)(short)(v[i] & 0xffff);
            int b = (int)(short)(v[i] >> 16);
            int colw = lane + 32 * i;
            if (a <= thr) {
                int p = atomicAdd(&ccnt[r], 1);
                if (p < CCAP) clist[r * CCAP + p] = 2 * colw;
            }
            if (b <= thr) {
                int p = atomicAdd(&ccnt[r], 1);
                if (p < CCAP) clist[r * CCAP + p] = 2 * colw + 1;
            }
        }
        if (lane == 0) minqs[r] = mn;
    }
    __syncthreads();

    // ---- warp-parallel exact fp32 rescue (warp w owns rows 8w..8w+7) ----
    for (int rr = 0; rr < 8; rr++) {
        int r = wid * 8 + rr;
        const float z2f = z2s[r];
        const float* zr = z + (size_t)(m0 + r) * DIM;
        float zv[8];
        #pragma unroll
        for (int i = 0; i < 8; i++) zv[i] = zr[lane + 32 * i];

        float best = CUDART_INF_F; int bi = 0x7fffffff;
        int cnt = ccnt[r];
        int n_check = (cnt <= CCAP) ? cnt : NE;
        for (int p = 0; p < n_check; p++) {
            int cidx = (cnt <= CCAP) ? clist[r * CCAP + p] : p;
            const float* cr = cb + (size_t)cidx * DIM;
            float part = 0.0f;
            #pragma unroll
            for (int i = 0; i < 8; i++)
                part = fmaf(zv[i], __ldg(cr + lane + 32 * i), part);
            #pragma unroll
            for (int o = 16; o; o >>= 1)
                part += __shfl_xor_sync(0xffffffffu, part, o);
            float dd = (z2f - 2.0f * part) + e2s[cidx];
            if (dd < best || (dd == best && cidx < bi)) { best = dd; bi = cidx; }
        }
        if (lane == 0) bi_s[r] = bi;
    }
    __syncthreads();

    // ---- epilogue: z_q_st (exact ST rounding), indices, loss ----
    float lacc = 0.0f;
    #pragma unroll 4
    for (int it = 0; it < MCTA; it++) {
        float zv = z[(size_t)(m0 + it) * DIM + tid];
        float e  = __ldg(cb + (size_t)bi_s[it] * DIM + tid);
        float dq = e - zv;                  // fl(z_q - z)
        float o  = zv + dq;                 // fl(z + fl(z_q - z))
        out[(size_t)(m0 + it) * DIM + tid] = o;
        lacc = fmaf(dq, dq, lacc);
    }
    if (tid < MCTA)
        out[(size_t)NT * DIM + 1 + m0 + tid] = (float)bi_s[tid];

    double* red = (double*)(smem + SRED);
    red[tid] = (double)lacc;
    __syncthreads();
    #pragma unroll
    for (int s = 128; s > 0; s >>= 1) {
        if (tid < s) red[tid] += red[tid + s];
        __syncthreads();
    }
    if (tid == 0) atomicAdd(&g_loss_acc, red[0]);
}

__global__ void vq_loss_kernel(float* __restrict__ out) {
    out[(size_t)NT * DIM] = (float)(1.25 * g_loss_acc / ((double)NT * (double)DIM));
}

// ---------------------------------------------------------------------------
extern "C" void kernel_launch(void* const* d_in, const int* in_sizes, int n_in,
                              void* d_out, int out_size) {
    const float *z, *cb;
    if (in_sizes[0] == NT * DIM) { z = (const float*)d_in[0]; cb = (const float*)d_in[1]; }
    else                         { z = (const float*)d_in[1]; cb = (const float*)d_in[0]; }
    float* out = (float*)d_out;

    cudaFuncSetAttribute(vq_main_kernel,
                         cudaFuncAttributeMaxDynamicSharedMemorySize, SMEM_TOTAL);

    vq_prep1_kernel<<<32, 256>>>(cb);
    vq_prep2_kernel<<<32, 256>>>(cb);
    vq_main_kernel<<<NT / MCTA, 256, SMEM_TOTAL>>>(z, cb, out);
    vq_loss_kernel<<<1, 1>>>(out);
}

// round 12
// speedup vs baseline: 157.5087x; 1.0138x over previous
#include <cuda_runtime.h>
#include <cstdint>
#include <math_constants.h>

#define NT     65536
#define DIM    256
#define NE     1024
#define MCTA   64
#define CCAP   48

// ---------------- smem layout (bytes) ----------------
#define SA8   0              // z tile int8: 64 rows x 72 words (pair-permuted)   18432
#define SBB   18432          // 4 B chunk buffers x 10240 (k64 chunks)            40960
#define SQD   59392          // qd: 64 rows x 516 u32 words (s16 pairs)          132096
#define SE2   191488         // e2 all 1024 f32                                    4096
#define SZ2   195584         // row norms f32 [64]                                  256
#define SINV  195840         // per-row inv dot scale f32 [64]                      256
#define SWQ   196096         // per-row capture window (q units) [64] int           256
#define SSZ   196352         // per-row z quant scale f32 [64]                      256
#define SCN   196608         // cand count [64] int                                 256
#define SMINQ 196864         // min q per row [64] int                              256
#define SBI   197120         // best index [64] int                                 256
#define SCL   197376         // cand list [64][CCAP] int                          12288
#define SRED  209664         // loss reduction [256] double                        2048
#define SMEM_TOTAL 211712

#define A8_STRIDE_W  72
#define B_STRIDE_W   20      // 16 data + 4 pad words per code row in chunk
#define BBUF_BYTES   10240
#define QD_STRIDE_W  516

__device__ double g_loss_acc;
__device__ float  g_e2[NE];
__device__ unsigned g_cbmax_bits;
__device__ unsigned g_scmax_bits;
// pair-permuted int8 codebook: per code 256 bytes = 8 groups of 32 k;
// within each group's 8 words, stored[2q]=orig[q], stored[2q+1]=orig[q+4]
__device__ __align__(16) signed char g_cb8[NE * DIM];

#define CP16(dst, src) asm volatile("cp.async.cg.shared.global [%0], [%1], 16;" :: "r"(dst), "l"(src) : "memory")
#define CP_COMMIT()    asm volatile("cp.async.commit_group;" ::: "memory")
#define CP_WAIT2()     asm volatile("cp.async.wait_group 2;" ::: "memory")

__device__ __forceinline__ uint32_t smem_u32(const void* p) {
    uint32_t a;
    asm("{ .reg .u64 t; cvta.to.shared.u64 t, %1; cvt.u32.u64 %0, t; }" : "=r"(a) : "l"(p));
    return a;
}

__device__ __forceinline__ void mma_s8(int& c0, int& c1, int& c2, int& c3,
                                       uint32_t a0, uint32_t a1, uint32_t a2, uint32_t a3,
                                       uint32_t b0, uint32_t b1) {
    asm volatile("mma.sync.aligned.m16n8k32.row.col.s32.s8.s8.s32 "
                 "{%0,%1,%2,%3},{%4,%5,%6,%7},{%8,%9},{%0,%1,%2,%3};"
                 : "+r"(c0), "+r"(c1), "+r"(c2), "+r"(c3)
                 : "r"(a0), "r"(a1), "r"(a2), "r"(a3), "r"(b0), "r"(b1));
}

__device__ __forceinline__ int quant8(float v, float s) {
    int x = __float2int_rn(v * s);
    return max(-127, min(127, x));
}

// ---------------- prep1: e2 (fp64) + cb stats + zero loss ----------------
__global__ void vq_prep1_kernel(const float* __restrict__ cb) {
    int tid = threadIdx.x, lane = tid & 31;
    if (blockIdx.x == 0 && tid == 0) g_loss_acc = 0.0;
    int gw = blockIdx.x * 8 + (tid >> 5);
    #pragma unroll
    for (int i = 0; i < 4; i++) {
        int c = gw * 4 + i;
        const float* row = cb + (size_t)c * DIM;
        double s = 0.0; float sa = 0.0f, mx = 0.0f;
        #pragma unroll
        for (int j = 0; j < 8; j++) {
            float v = row[lane + 32 * j];
            s += (double)v * (double)v;
            sa += fabsf(v);
            mx = fmaxf(mx, fabsf(v));
        }
        #pragma unroll
        for (int o = 16; o; o >>= 1) {
            s  += __shfl_xor_sync(0xffffffffu, s, o);
            sa += __shfl_xor_sync(0xffffffffu, sa, o);
            mx = fmaxf(mx, __shfl_xor_sync(0xffffffffu, mx, o));
        }
        if (lane == 0) {
            g_e2[c] = (float)s;
            atomicMax(&g_cbmax_bits, __float_as_uint(mx));
            atomicMax(&g_scmax_bits, __float_as_uint(sa));
        }
    }
}

// ---------------- prep2: quantize codebook int8 pair-permuted ----------------
__global__ void vq_prep2_kernel(const float* __restrict__ cb) {
    float cbmax = __uint_as_float(g_cbmax_bits);
    float sc = (cbmax > 0.0f) ? 126.0f / cbmax : 1.0f;
    uint32_t* out8 = (uint32_t*)g_cb8;
    int base = blockIdx.x * 256 + threadIdx.x;
    #pragma unroll
    for (int i = 0; i < 8; i++) {
        int w = base + i * 8192;
        int n = w >> 6, m = w & 63;
        int G = m >> 3, p = m & 7;
        int o = (p & 1) ? ((p >> 1) + 4) : (p >> 1);
        int k0 = G * 32 + o * 4;
        const float* src = cb + (size_t)n * DIM + k0;
        int b0 = quant8(src[0], sc), b1 = quant8(src[1], sc);
        int b2 = quant8(src[2], sc), b3 = quant8(src[3], sc);
        out8[w] = (uint32_t)(b0 & 0xff) | ((uint32_t)(b1 & 0xff) << 8)
                | ((uint32_t)(b2 & 0xff) << 16) | ((uint32_t)(b3 & 0xff) << 24);
    }
}

// ---------------- main ----------------
__global__ __launch_bounds__(256) void vq_main_kernel(
    const float* __restrict__ z,
    const float* __restrict__ cb,
    float* __restrict__ out)
{
    extern __shared__ char smem[];
    const uint32_t sbu = smem_u32(smem);
    uint32_t* a8w   = (uint32_t*)(smem + SA8);
    uint32_t* qd    = (uint32_t*)(smem + SQD);
    float*    e2s   = (float*)(smem + SE2);
    float*    z2s   = (float*)(smem + SZ2);
    float*    invs  = (float*)(smem + SINV);
    int*      wqs   = (int*)(smem + SWQ);
    float*    szs   = (float*)(smem + SSZ);
    int*      ccnt  = (int*)(smem + SCN);
    int*      minqs = (int*)(smem + SMINQ);
    int*      bi_s  = (int*)(smem + SBI);
    int*      clist = (int*)(smem + SCL);

    const int tid  = threadIdx.x;
    const int wid  = tid >> 5;
    const int lane = tid & 31;
    const int q    = lane & 3;
    const int lq   = lane >> 2;
    const int m0   = blockIdx.x * MCTA;
    const int rw   = (wid & 3) * 16;
    const int nb2  = (wid >> 2);

    const float cbmax = __uint_as_float(g_cbmax_bits);
    const float scmax = __uint_as_float(g_scmax_bits);
    const float sc  = (cbmax > 0.0f) ? 126.0f / cbmax : 1.0f;
    const float dcq = 0.5f / sc;

    // ---- e2 table, init ----
    #pragma unroll
    for (int i = 0; i < 4; i++) e2s[i * 256 + tid] = g_e2[i * 256 + tid];
    if (tid < MCTA) ccnt[tid] = 0;

    // ---- per-row stats (fp64 z2, sum|z|, max|z|) -> scale/inv/window ----
    #pragma unroll
    for (int rr = 0; rr < 8; rr++) {
        int r = wid * 8 + rr;
        const float* zr = z + (size_t)(m0 + r) * DIM;
        double s = 0.0; float sa = 0.0f, mx = 0.0f;
        #pragma unroll
        for (int i = 0; i < 8; i++) {
            float v = zr[lane + 32 * i];
            s += (double)v * (double)v;
            sa += fabsf(v);
            mx = fmaxf(mx, fabsf(v));
        }
        #pragma unroll
        for (int o = 16; o; o >>= 1) {
            s  += __shfl_xor_sync(0xffffffffu, s, o);
            sa += __shfl_xor_sync(0xffffffffu, sa, o);
            mx = fmaxf(mx, __shfl_xor_sync(0xffffffffu, mx, o));
        }
        if (lane == 0) {
            float sz = (mx > 0.0f) ? 126.0f / mx : 1.0f;
            float dzr = 0.5f / sz;
            float E = dzr * scmax + dcq * sa + 256.0f * dzr * dcq;  // hard dot-err bound
            z2s[r]  = (float)s;
            szs[r]  = sz;
            invs[r] = 1.0f / (sz * sc);
            wqs[r]  = (int)(4.0f * E * 32768.0f) + 8;
        }
    }
    __syncthreads();

    // ---- stage A int8 pair-permuted ----
    #pragma unroll
    for (int i = 0; i < 16; i++) {
        int s = i * 256 + tid;
        int row = s >> 6, ow = s & 63;
        int G = ow >> 3, o = ow & 7;
        int k0 = G * 32 + o * 4;
        float sz = szs[row];
        const float* src = z + (size_t)(m0 + row) * DIM + k0;
        int b0 = quant8(src[0], sz), b1 = quant8(src[1], sz);
        int b2 = quant8(src[2], sz), b3 = quant8(src[3], sz);
        int dw = (o < 4) ? 2 * o : 2 * (o - 4) + 1;
        a8w[row * A8_STRIDE_W + G * 8 + dw] =
            (uint32_t)(b0 & 0xff) | ((uint32_t)(b1 & 0xff) << 8)
          | ((uint32_t)(b2 & 0xff) << 16) | ((uint32_t)(b3 & 0xff) << 24);
    }
    __syncthreads();

    // ---- B chunk loader: chunk c -> ntile c>>2, k64-chunk c&3, buffer c&3 ----
    auto load_chunk = [&](int c) {
        int nt = c >> 2, kc = c & 3;
        const char* src0 = (const char*)g_cb8 + (size_t)nt * 128 * 256 + kc * 64;
        uint32_t bbase = sbu + SBB + (c & 3) * BBUF_BYTES;
        #pragma unroll
        for (int i = 0; i < 2; i++) {
            int s = i * 256 + tid;
            int n = s >> 2, seg = s & 3;
            CP16(bbase + n * 80 + seg * 16, src0 + (size_t)n * 256 + seg * 16);
        }
    };
    load_chunk(0); CP_COMMIT();
    load_chunk(1); CP_COMMIT();
    load_chunk(2); CP_COMMIT();

    int acc[8][4];
    #pragma unroll
    for (int j = 0; j < 8; j++)
        #pragma unroll
        for (int e = 0; e < 4; e++) acc[j][e] = 0;

    const int r0 = rw + lq;
    const float inv0 = invs[r0], inv1 = invs[r0 + 8];

    for (int c = 0; c < 32; c++) {
        const int nt = c >> 2, kc = c & 3;
        CP_WAIT2();           // chunk c resident (per-thread)
        __syncthreads();      // all threads' waits done; buffer (c-1)&3 free
        if (c + 3 < 32) load_chunk(c + 3);
        CP_COMMIT();          // uniform group cadence

        const uint32_t* Bw = (const uint32_t*)(smem + SBB + (c & 3) * BBUF_BYTES);
        #pragma unroll
        for (int g = 0; g < 2; g++) {
            const int aw = (kc * 2 + g) * 8 + 2 * q;
            uint2 A0 = *(const uint2*)(a8w + r0 * A8_STRIDE_W + aw);
            uint2 A1 = *(const uint2*)(a8w + (r0 + 8) * A8_STRIDE_W + aw);
            #pragma unroll
            for (int j = 0; j < 8; j++) {
                int nl = nb2 * 64 + 8 * j + lq;
                uint2 B0 = *(const uint2*)(Bw + nl * B_STRIDE_W + g * 8 + 2 * q);
                mma_s8(acc[j][0], acc[j][1], acc[j][2], acc[j][3],
                       A0.x, A1.x, A0.y, A1.y, B0.x, B0.y);
            }
        }

        if (kc == 3) {
            // q16 = round((e2 - 2*isum*inv) * 2^15)
            #pragma unroll
            for (int j = 0; j < 8; j++) {
                int col0 = nt * 128 + nb2 * 64 + 8 * j + 2 * q;
                float e20 = e2s[col0], e21 = e2s[col0 + 1];
                int wIdx = (col0 >> 1);
                #pragma unroll
                for (int h = 0; h < 2; h++) {
                    float inv = h ? inv1 : inv0;
                    float s0 = e20 - 2.0f * ((float)acc[j][h * 2 + 0] * inv);
                    float s1 = e21 - 2.0f * ((float)acc[j][h * 2 + 1] * inv);
                    int q0 = max(-32767, min(32767, __float2int_rn(s0 * 32768.0f)));
                    int q1 = max(-32767, min(32767, __float2int_rn(s1 * 32768.0f)));
                    qd[(r0 + 8 * h) * QD_STRIDE_W + wIdx] =
                        ((uint32_t)(q1 & 0xffff) << 16) | (uint32_t)(q0 & 0xffff);
                    acc[j][h * 2 + 0] = 0;
                    acc[j][h * 2 + 1] = 0;
                }
            }
        }
    }
    __syncthreads();

    // ---- per-row FINAL min + capture vs hard per-row window (uint4 loads) ----
    for (int rr = 0; rr < 8; rr++) {
        int r = wid * 8 + rr;
        const uint4* row4 = (const uint4*)(qd + r * QD_STRIDE_W);
        uint4 v[4];
        int mn = 0x7fffffff;
        #pragma unroll
        for (int i = 0; i < 4; i++) {
            v[i] = row4[lane + 32 * i];
            const uint32_t* vw = (const uint32_t*)&v[i];
            #pragma unroll
            for (int w = 0; w < 4; w++) {
                int a = (int)(short)(vw[w] & 0xffff);
                int b = (int)(short)(vw[w] >> 16);
                mn = min(mn, min(a, b));
            }
        }
        #pragma unroll
        for (int o = 16; o; o >>= 1) mn = min(mn, __shfl_xor_sync(0xffffffffu, mn, o));
        int thr = mn + wqs[r];
        #pragma unroll
        for (int i = 0; i < 4; i++) {
            const uint32_t* vw = (const uint32_t*)&v[i];
            #pragma unroll
            for (int w = 0; w < 4; w++) {
                int a = (int)(short)(vw[w] & 0xffff);
                int b = (int)(short)(vw[w] >> 16);
                int colw = (lane + 32 * i) * 4 + w;
                if (a <= thr) {
                    int p = atomicAdd(&ccnt[r], 1);
                    if (p < CCAP) clist[r * CCAP + p] = 2 * colw;
                }
                if (b <= thr) {
                    int p = atomicAdd(&ccnt[r], 1);
                    if (p < CCAP) clist[r * CCAP + p] = 2 * colw + 1;
                }
            }
        }
        if (lane == 0) minqs[r] = mn;
    }
    __syncthreads();

    // ---- warp-parallel exact fp32 rescue (warp w owns rows 8w..8w+7) ----
    for (int rr = 0; rr < 8; rr++) {
        int r = wid * 8 + rr;
        const float z2f = z2s[r];
        const float* zr = z + (size_t)(m0 + r) * DIM;
        float zv[8];
        #pragma unroll
        for (int i = 0; i < 8; i++) zv[i] = zr[lane + 32 * i];

        float best = CUDART_INF_F; int bi = 0x7fffffff;
        int cnt = ccnt[r];
        int n_check = (cnt <= CCAP) ? cnt : NE;
        for (int p = 0; p < n_check; p++) {
            int cidx = (cnt <= CCAP) ? clist[r * CCAP + p] : p;
            const float* cr = cb + (size_t)cidx * DIM;
            float part = 0.0f;
            #pragma unroll
            for (int i = 0; i < 8; i++)
                part = fmaf(zv[i], __ldg(cr + lane + 32 * i), part);
            #pragma unroll
            for (int o = 16; o; o >>= 1)
                part += __shfl_xor_sync(0xffffffffu, part, o);
            float dd = (z2f - 2.0f * part) + e2s[cidx];
            if (dd < best || (dd == best && cidx < bi)) { best = dd; bi = cidx; }
        }
        if (lane == 0) bi_s[r] = bi;
    }
    __syncthreads();

    // ---- epilogue: z_q_st (exact ST rounding), indices, loss ----
    float lacc = 0.0f;
    #pragma unroll 4
    for (int it = 0; it < MCTA; it++) {
        float zv = z[(size_t)(m0 + it) * DIM + tid];
        float e  = __ldg(cb + (size_t)bi_s[it] * DIM + tid);
        float dq = e - zv;                  // fl(z_q - z)
        float o  = zv + dq;                 // fl(z + fl(z_q - z))
        out[(size_t)(m0 + it) * DIM + tid] = o;
        lacc = fmaf(dq, dq, lacc);
    }
    if (tid < MCTA)
        out[(size_t)NT * DIM + 1 + m0 + tid] = (float)bi_s[tid];

    double* red = (double*)(smem + SRED);
    red[tid] = (double)lacc;
    __syncthreads();
    #pragma unroll
    for (int s = 128; s > 0; s >>= 1) {
        if (tid < s) red[tid] += red[tid + s];
        __syncthreads();
    }
    if (tid == 0) atomicAdd(&g_loss_acc, red[0]);
}

__global__ void vq_loss_kernel(float* __restrict__ out) {
    out[(size_t)NT * DIM] = (float)(1.25 * g_loss_acc / ((double)NT * (double)DIM));
}

// ---------------------------------------------------------------------------
extern "C" void kernel_launch(void* const* d_in, const int* in_sizes, int n_in,
                              void* d_out, int out_size) {
    const float *z, *cb;
    if (in_sizes[0] == NT * DIM) { z = (const float*)d_in[0]; cb = (const float*)d_in[1]; }
    else                         { z = (const float*)d_in[1]; cb = (const float*)d_in[0]; }
    float* out = (float*)d_out;

    cudaFuncSetAttribute(vq_main_kernel,
                         cudaFuncAttributeMaxDynamicSharedMemorySize, SMEM_TOTAL);

    vq_prep1_kernel<<<32, 256>>>(cb);
    vq_prep2_kernel<<<32, 256>>>(cb);
    vq_main_kernel<<<NT / MCTA, 256, SMEM_TOTAL>>>(z, cb, out);
    vq_loss_kernel<<<1, 1>>>(out);
}

// round 13
// speedup vs baseline: 205.2965x; 1.3034x over previous
#include <cuda_runtime.h>
#include <cstdint>
#include <math_constants.h>

#define NT     65536
#define DIM    256
#define NE     1024
#define MCTA   64
#define BLOCK  512
#define CCAP   48

// ---------------- smem layout (bytes) ----------------
#define SA8   0              // z tile int8: 64 rows x 72 words (pair-permuted)   18432
#define SBB   18432          // 4 B chunk buffers x 10240 (k64 chunks)            40960
#define SQD   59392          // qd: 64 rows x 516 u32 words (s16 pairs)          132096
#define SE2   191488         // e2 all 1024 f32                                    4096
#define SZ2   195584         // row norms f32 [64]                                  256
#define SINV  195840         // per-row inv dot scale f32 [64]                      256
#define SWQ   196096         // per-row capture window (q units) [64] int           256
#define SSZ   196352         // per-row z quant scale f32 [64]                      256
#define SCN   196608         // cand count [64] int                                 256
#define SMINQ 196864         // min q per row [64] int                              256
#define SBI   197120         // best index [64] int                                 256
#define SCL   197376         // cand list [64][CCAP] int                          12288
#define SRED  209664         // loss reduction [512] double                        4096
#define SMEM_TOTAL 213760

#define A8_STRIDE_W  72
#define B_STRIDE_W   20      // 16 data + 4 pad words per code row in chunk
#define BBUF_BYTES   10240
#define QD_STRIDE_W  516

__device__ double g_loss_acc;
__device__ float  g_e2[NE];
__device__ unsigned g_cbmax_bits;
__device__ unsigned g_scmax_bits;
// pair-permuted int8 codebook: per code 256 bytes = 8 groups of 32 k;
// within each group's 8 words, stored[2q]=orig[q], stored[2q+1]=orig[q+4]
__device__ __align__(16) signed char g_cb8[NE * DIM];

#define CP16(dst, src) asm volatile("cp.async.cg.shared.global [%0], [%1], 16;" :: "r"(dst), "l"(src) : "memory")
#define CP_COMMIT()    asm volatile("cp.async.commit_group;" ::: "memory")
#define CP_WAIT2()     asm volatile("cp.async.wait_group 2;" ::: "memory")

__device__ __forceinline__ uint32_t smem_u32(const void* p) {
    uint32_t a;
    asm("{ .reg .u64 t; cvta.to.shared.u64 t, %1; cvt.u32.u64 %0, t; }" : "=r"(a) : "l"(p));
    return a;
}

__device__ __forceinline__ void mma_s8(int& c0, int& c1, int& c2, int& c3,
                                       uint32_t a0, uint32_t a1, uint32_t a2, uint32_t a3,
                                       uint32_t b0, uint32_t b1) {
    asm volatile("mma.sync.aligned.m16n8k32.row.col.s32.s8.s8.s32 "
                 "{%0,%1,%2,%3},{%4,%5,%6,%7},{%8,%9},{%0,%1,%2,%3};"
                 : "+r"(c0), "+r"(c1), "+r"(c2), "+r"(c3)
                 : "r"(a0), "r"(a1), "r"(a2), "r"(a3), "r"(b0), "r"(b1));
}

__device__ __forceinline__ int quant8(float v, float s) {
    int x = __float2int_rn(v * s);
    return max(-127, min(127, x));
}

// ---------------- prep1: e2 (fp64) + cb stats + zero loss ----------------
__global__ void vq_prep1_kernel(const float* __restrict__ cb) {
    int tid = threadIdx.x, lane = tid & 31;
    if (blockIdx.x == 0 && tid == 0) g_loss_acc = 0.0;
    int gw = blockIdx.x * 8 + (tid >> 5);
    #pragma unroll
    for (int i = 0; i < 4; i++) {
        int c = gw * 4 + i;
        const float* row = cb + (size_t)c * DIM;
        double s = 0.0; float sa = 0.0f, mx = 0.0f;
        #pragma unroll
        for (int j = 0; j < 8; j++) {
            float v = row[lane + 32 * j];
            s += (double)v * (double)v;
            sa += fabsf(v);
            mx = fmaxf(mx, fabsf(v));
        }
        #pragma unroll
        for (int o = 16; o; o >>= 1) {
            s  += __shfl_xor_sync(0xffffffffu, s, o);
            sa += __shfl_xor_sync(0xffffffffu, sa, o);
            mx = fmaxf(mx, __shfl_xor_sync(0xffffffffu, mx, o));
        }
        if (lane == 0) {
            g_e2[c] = (float)s;
            atomicMax(&g_cbmax_bits, __float_as_uint(mx));
            atomicMax(&g_scmax_bits, __float_as_uint(sa));
        }
    }
}

// ---------------- prep2: quantize codebook int8 pair-permuted ----------------
__global__ void vq_prep2_kernel(const float* __restrict__ cb) {
    float cbmax = __uint_as_float(g_cbmax_bits);
    float sc = (cbmax > 0.0f) ? 126.0f / cbmax : 1.0f;
    uint32_t* out8 = (uint32_t*)g_cb8;
    int base = blockIdx.x * 256 + threadIdx.x;
    #pragma unroll
    for (int i = 0; i < 8; i++) {
        int w = base + i * 8192;
        int n = w >> 6, m = w & 63;
        int G = m >> 3, p = m & 7;
        int o = (p & 1) ? ((p >> 1) + 4) : (p >> 1);
        int k0 = G * 32 + o * 4;
        const float* src = cb + (size_t)n * DIM + k0;
        int b0 = quant8(src[0], sc), b1 = quant8(src[1], sc);
        int b2 = quant8(src[2], sc), b3 = quant8(src[3], sc);
        out8[w] = (uint32_t)(b0 & 0xff) | ((uint32_t)(b1 & 0xff) << 8)
                | ((uint32_t)(b2 & 0xff) << 16) | ((uint32_t)(b3 & 0xff) << 24);
    }
}

// ---------------- main: 512 threads, 16 warps (4 M x 4 N) ----------------
__global__ __launch_bounds__(BLOCK) void vq_main_kernel(
    const float* __restrict__ z,
    const float* __restrict__ cb,
    float* __restrict__ out)
{
    extern __shared__ char smem[];
    const uint32_t sbu = smem_u32(smem);
    uint32_t* a8w   = (uint32_t*)(smem + SA8);
    uint32_t* qd    = (uint32_t*)(smem + SQD);
    float*    e2s   = (float*)(smem + SE2);
    float*    z2s   = (float*)(smem + SZ2);
    float*    invs  = (float*)(smem + SINV);
    int*      wqs   = (int*)(smem + SWQ);
    float*    szs   = (float*)(smem + SSZ);
    int*      ccnt  = (int*)(smem + SCN);
    int*      minqs = (int*)(smem + SMINQ);
    int*      bi_s  = (int*)(smem + SBI);
    int*      clist = (int*)(smem + SCL);

    const int tid  = threadIdx.x;
    const int wid  = tid >> 5;
    const int lane = tid & 31;
    const int q    = lane & 3;
    const int lq   = lane >> 2;
    const int m0   = blockIdx.x * MCTA;
    const int mw   = (wid & 3) * 16;     // warp M base (4 warps in M)
    const int nw   = (wid >> 2) * 32;    // warp N base within 128-ntile (4 warps in N)

    const float cbmax = __uint_as_float(g_cbmax_bits);
    const float scmax = __uint_as_float(g_scmax_bits);
    const float sc  = (cbmax > 0.0f) ? 126.0f / cbmax : 1.0f;
    const float dcq = 0.5f / sc;

    // ---- e2 table, init ----
    #pragma unroll
    for (int i = 0; i < 2; i++) e2s[i * BLOCK + tid] = g_e2[i * BLOCK + tid];
    if (tid < MCTA) ccnt[tid] = 0;

    // ---- per-row stats (fp64 z2, sum|z|, max|z|): warp w owns rows 4w..4w+3 ----
    #pragma unroll
    for (int rr = 0; rr < 4; rr++) {
        int r = wid * 4 + rr;
        const float* zr = z + (size_t)(m0 + r) * DIM;
        double s = 0.0; float sa = 0.0f, mx = 0.0f;
        #pragma unroll
        for (int i = 0; i < 8; i++) {
            float v = zr[lane + 32 * i];
            s += (double)v * (double)v;
            sa += fabsf(v);
            mx = fmaxf(mx, fabsf(v));
        }
        #pragma unroll
        for (int o = 16; o; o >>= 1) {
            s  += __shfl_xor_sync(0xffffffffu, s, o);
            sa += __shfl_xor_sync(0xffffffffu, sa, o);
            mx = fmaxf(mx, __shfl_xor_sync(0xffffffffu, mx, o));
        }
        if (lane == 0) {
            float sz = (mx > 0.0f) ? 126.0f / mx : 1.0f;
            float dzr = 0.5f / sz;
            float E = dzr * scmax + dcq * sa + 256.0f * dzr * dcq;  // hard dot-err bound
            z2s[r]  = (float)s;
            szs[r]  = sz;
            invs[r] = 1.0f / (sz * sc);
            wqs[r]  = (int)(4.0f * E * 32768.0f) + 8;
        }
    }
    __syncthreads();

    // ---- stage A int8 pair-permuted (4096 words) ----
    #pragma unroll
    for (int i = 0; i < 8; i++) {
        int s = i * BLOCK + tid;
        int row = s >> 6, ow = s & 63;
        int G = ow >> 3, o = ow & 7;
        int k0 = G * 32 + o * 4;
        float sz = szs[row];
        const float* src = z + (size_t)(m0 + row) * DIM + k0;
        int b0 = quant8(src[0], sz), b1 = quant8(src[1], sz);
        int b2 = quant8(src[2], sz), b3 = quant8(src[3], sz);
        int dw = (o < 4) ? 2 * o : 2 * (o - 4) + 1;
        a8w[row * A8_STRIDE_W + G * 8 + dw] =
            (uint32_t)(b0 & 0xff) | ((uint32_t)(b1 & 0xff) << 8)
          | ((uint32_t)(b2 & 0xff) << 16) | ((uint32_t)(b3 & 0xff) << 24);
    }
    __syncthreads();

    // ---- B chunk loader: chunk c -> ntile c>>2, k64-chunk c&3, buffer c&3 ----
    auto load_chunk = [&](int c) {
        int nt = c >> 2, kc = c & 3;
        const char* src0 = (const char*)g_cb8 + (size_t)nt * 128 * 256 + kc * 64;
        uint32_t bbase = sbu + SBB + (c & 3) * BBUF_BYTES;
        {   // 512 16B segs, one per thread
            int n = tid >> 2, seg = tid & 3;
            CP16(bbase + n * 80 + seg * 16, src0 + (size_t)n * 256 + seg * 16);
        }
    };
    load_chunk(0); CP_COMMIT();
    load_chunk(1); CP_COMMIT();
    load_chunk(2); CP_COMMIT();

    int acc[4][4];
    #pragma unroll
    for (int j = 0; j < 4; j++)
        #pragma unroll
        for (int e = 0; e < 4; e++) acc[j][e] = 0;

    const int r0 = mw + lq;
    const float inv0 = invs[r0], inv1 = invs[r0 + 8];

    for (int c = 0; c < 32; c++) {
        const int nt = c >> 2, kc = c & 3;
        CP_WAIT2();           // chunk c resident (per-thread)
        __syncthreads();      // all threads' waits done; buffer (c-1)&3 free
        if (c + 3 < 32) load_chunk(c + 3);
        CP_COMMIT();          // uniform group cadence

        const uint32_t* Bw = (const uint32_t*)(smem + SBB + (c & 3) * BBUF_BYTES);
        #pragma unroll
        for (int g = 0; g < 2; g++) {
            const int aw = (kc * 2 + g) * 8 + 2 * q;
            uint2 A0 = *(const uint2*)(a8w + r0 * A8_STRIDE_W + aw);
            uint2 A1 = *(const uint2*)(a8w + (r0 + 8) * A8_STRIDE_W + aw);
            #pragma unroll
            for (int j = 0; j < 4; j++) {
                int nl = nw + 8 * j + lq;
                uint2 B0 = *(const uint2*)(Bw + nl * B_STRIDE_W + g * 8 + 2 * q);
                mma_s8(acc[j][0], acc[j][1], acc[j][2], acc[j][3],
                       A0.x, A1.x, A0.y, A1.y, B0.x, B0.y);
            }
        }

        if (kc == 3) {
            // q16 = round((e2 - 2*isum*inv) * 2^15)
            #pragma unroll
            for (int j = 0; j < 4; j++) {
                int col0 = nt * 128 + nw + 8 * j + 2 * q;
                float e20 = e2s[col0], e21 = e2s[col0 + 1];
                int wIdx = (col0 >> 1);
                #pragma unroll
                for (int h = 0; h < 2; h++) {
                    float inv = h ? inv1 : inv0;
                    float s0 = e20 - 2.0f * ((float)acc[j][h * 2 + 0] * inv);
                    float s1 = e21 - 2.0f * ((float)acc[j][h * 2 + 1] * inv);
                    int q0 = max(-32767, min(32767, __float2int_rn(s0 * 32768.0f)));
                    int q1 = max(-32767, min(32767, __float2int_rn(s1 * 32768.0f)));
                    qd[(r0 + 8 * h) * QD_STRIDE_W + wIdx] =
                        ((uint32_t)(q1 & 0xffff) << 16) | (uint32_t)(q0 & 0xffff);
                    acc[j][h * 2 + 0] = 0;
                    acc[j][h * 2 + 1] = 0;
                }
            }
        }
    }
    __syncthreads();

    // ---- per-row FINAL min + capture (warp w owns rows 4w..4w+3, uint4 loads) ----
    for (int rr = 0; rr < 4; rr++) {
        int r = wid * 4 + rr;
        const uint4* row4 = (const uint4*)(qd + r * QD_STRIDE_W);
        uint4 v[4];
        int mn = 0x7fffffff;
        #pragma unroll
        for (int i = 0; i < 4; i++) {
            v[i] = row4[lane + 32 * i];
            const uint32_t* vw = (const uint32_t*)&v[i];
            #pragma unroll
            for (int w = 0; w < 4; w++) {
                int a = (int)(short)(vw[w] & 0xffff);
                int b = (int)(short)(vw[w] >> 16);
                mn = min(mn, min(a, b));
            }
        }
        #pragma unroll
        for (int o = 16; o; o >>= 1) mn = min(mn, __shfl_xor_sync(0xffffffffu, mn, o));
        int thr = mn + wqs[r];
        #pragma unroll
        for (int i = 0; i < 4; i++) {
            const uint32_t* vw = (const uint32_t*)&v[i];
            #pragma unroll
            for (int w = 0; w < 4; w++) {
                int a = (int)(short)(vw[w] & 0xffff);
                int b = (int)(short)(vw[w] >> 16);
                int colw = (lane + 32 * i) * 4 + w;
                if (a <= thr) {
                    int p = atomicAdd(&ccnt[r], 1);
                    if (p < CCAP) clist[r * CCAP + p] = 2 * colw;
                }
                if (b <= thr) {
                    int p = atomicAdd(&ccnt[r], 1);
                    if (p < CCAP) clist[r * CCAP + p] = 2 * colw + 1;
                }
            }
        }
        if (lane == 0) minqs[r] = mn;
    }
    __syncthreads();

    // ---- warp-parallel exact fp32 rescue (warp w owns rows 4w..4w+3) ----
    for (int rr = 0; rr < 4; rr++) {
        int r = wid * 4 + rr;
        const float z2f = z2s[r];
        const float* zr = z + (size_t)(m0 + r) * DIM;
        float zv[8];
        #pragma unroll
        for (int i = 0; i < 8; i++) zv[i] = zr[lane + 32 * i];

        float best = CUDART_INF_F; int bi = 0x7fffffff;
        int cnt = ccnt[r];
        int n_check = (cnt <= CCAP) ? cnt : NE;
        for (int p = 0; p < n_check; p++) {
            int cidx = (cnt <= CCAP) ? clist[r * CCAP + p] : p;
            const float* cr = cb + (size_t)cidx * DIM;
            float part = 0.0f;
            #pragma unroll
            for (int i = 0; i < 8; i++)
                part = fmaf(zv[i], __ldg(cr + lane + 32 * i), part);
            #pragma unroll
            for (int o = 16; o; o >>= 1)
                part += __shfl_xor_sync(0xffffffffu, part, o);
            float dd = (z2f - 2.0f * part) + e2s[cidx];
            if (dd < best || (dd == best && cidx < bi)) { best = dd; bi = cidx; }
        }
        if (lane == 0) bi_s[r] = bi;
    }
    __syncthreads();

    // ---- epilogue: z_q_st (exact ST rounding), indices, loss ----
    const int half = tid >> 8;          // 0/1: rows [0,32) / [32,64)
    const int col  = tid & 255;
    float lacc = 0.0f;
    #pragma unroll 4
    for (int it = 0; it < 32; it++) {
        int row = half * 32 + it;
        float zv = z[(size_t)(m0 + row) * DIM + col];
        float e  = __ldg(cb + (size_t)bi_s[row] * DIM + col);
        float dq = e - zv;                  // fl(z_q - z)
        float o  = zv + dq;                 // fl(z + fl(z_q - z))
        out[(size_t)(m0 + row) * DIM + col] = o;
        lacc = fmaf(dq, dq, lacc);
    }
    if (tid < MCTA)
        out[(size_t)NT * DIM + 1 + m0 + tid] = (float)bi_s[tid];

    double* red = (double*)(smem + SRED);
    red[tid] = (double)lacc;
    __syncthreads();
    #pragma unroll
    for (int s = 256; s > 0; s >>= 1) {
        if (tid < s) red[tid] += red[tid + s];
        __syncthreads();
    }
    if (tid == 0) atomicAdd(&g_loss_acc, red[0]);
}

__global__ void vq_loss_kernel(float* __restrict__ out) {
    out[(size_t)NT * DIM] = (float)(1.25 * g_loss_acc / ((double)NT * (double)DIM));
}

// ---------------------------------------------------------------------------
extern "C" void kernel_launch(void* const* d_in, const int* in_sizes, int n_in,
                              void* d_out, int out_size) {
    const float *z, *cb;
    if (in_sizes[0] == NT * DIM) { z = (const float*)d_in[0]; cb = (const float*)d_in[1]; }
    else                         { z = (const float*)d_in[1]; cb = (const float*)d_in[0]; }
    float* out = (float*)d_out;

    cudaFuncSetAttribute(vq_main_kernel,
                         cudaFuncAttributeMaxDynamicSharedMemorySize, SMEM_TOTAL);

    vq_prep1_kernel<<<32, 256>>>(cb);
    vq_prep2_kernel<<<32, 256>>>(cb);
    vq_main_kernel<<<NT / MCTA, BLOCK, SMEM_TOTAL>>>(z, cb, out);
    vq_loss_kernel<<<1, 1>>>(out);
}

// round 14
// speedup vs baseline: 220.5726x; 1.0744x over previous
#include <cuda_runtime.h>
#include <cstdint>
#include <math_constants.h>

#define NT     65536
#define DIM    256
#define NE     1024
#define MCTA   64
#define BLOCK  1024
#define CCAP   48

// ---------------- smem layout (bytes) ----------------
#define SA8   0              // z tile int8: 64 rows x 72 words (pair-permuted)   18432
#define SBB   18432          // 4 B chunk buffers x 10240 (k64 chunks)            40960
#define SQD   59392          // qd: 64 rows x 516 u32 words (s16 pairs)          132096
#define SE2   191488         // e2 all 1024 f32                                    4096
#define SZ2   195584         // row norms f32 [64]                                  256
#define SINV  195840         // per-row inv dot scale f32 [64]                      256
#define SWQ   196096         // per-row capture window (q units) [64] int           256
#define SSZ   196352         // per-row z quant scale f32 [64]                      256
#define SCN   196608         // cand count [64] int                                 256
#define SMINQ 196864         // min q per row [64] int                              256
#define SBI   197120         // best index [64] int                                 256
#define SCL   197376         // cand list [64][CCAP] int                          12288
#define SRED  209664         // loss reduction [1024] double                       8192
#define SMEM_TOTAL 217856

#define A8_STRIDE_W  72
#define B_STRIDE_W   20      // 16 data + 4 pad words per code row in chunk
#define BBUF_BYTES   10240
#define QD_STRIDE_W  516

__device__ double g_loss_acc;
__device__ float  g_e2[NE];
__device__ unsigned g_cbmax_bits;
__device__ unsigned g_scmax_bits;
// pair-permuted int8 codebook: per code 256 bytes = 8 groups of 32 k;
// within each group's 8 words, stored[2q]=orig[q], stored[2q+1]=orig[q+4]
__device__ __align__(16) signed char g_cb8[NE * DIM];

#define CP16(dst, src) asm volatile("cp.async.cg.shared.global [%0], [%1], 16;" :: "r"(dst), "l"(src) : "memory")
#define CP_COMMIT()    asm volatile("cp.async.commit_group;" ::: "memory")
#define CP_WAIT2()     asm volatile("cp.async.wait_group 2;" ::: "memory")

__device__ __forceinline__ uint32_t smem_u32(const void* p) {
    uint32_t a;
    asm("{ .reg .u64 t; cvta.to.shared.u64 t, %1; cvt.u32.u64 %0, t; }" : "=r"(a) : "l"(p));
    return a;
}

__device__ __forceinline__ void mma_s8(int& c0, int& c1, int& c2, int& c3,
                                       uint32_t a0, uint32_t a1, uint32_t a2, uint32_t a3,
                                       uint32_t b0, uint32_t b1) {
    asm volatile("mma.sync.aligned.m16n8k32.row.col.s32.s8.s8.s32 "
                 "{%0,%1,%2,%3},{%4,%5,%6,%7},{%8,%9},{%0,%1,%2,%3};"
                 : "+r"(c0), "+r"(c1), "+r"(c2), "+r"(c3)
                 : "r"(a0), "r"(a1), "r"(a2), "r"(a3), "r"(b0), "r"(b1));
}

__device__ __forceinline__ int quant8(float v, float s) {
    int x = __float2int_rn(v * s);
    return max(-127, min(127, x));
}

// ---------------- prep1: e2 (fp64) + cb stats + zero loss ----------------
__global__ void vq_prep1_kernel(const float* __restrict__ cb) {
    int tid = threadIdx.x, lane = tid & 31;
    if (blockIdx.x == 0 && tid == 0) g_loss_acc = 0.0;
    int gw = blockIdx.x * 8 + (tid >> 5);
    #pragma unroll
    for (int i = 0; i < 4; i++) {
        int c = gw * 4 + i;
        const float* row = cb + (size_t)c * DIM;
        double s = 0.0; float sa = 0.0f, mx = 0.0f;
        #pragma unroll
        for (int j = 0; j < 8; j++) {
            float v = row[lane + 32 * j];
            s += (double)v * (double)v;
            sa += fabsf(v);
            mx = fmaxf(mx, fabsf(v));
        }
        #pragma unroll
        for (int o = 16; o; o >>= 1) {
            s  += __shfl_xor_sync(0xffffffffu, s, o);
            sa += __shfl_xor_sync(0xffffffffu, sa, o);
            mx = fmaxf(mx, __shfl_xor_sync(0xffffffffu, mx, o));
        }
        if (lane == 0) {
            g_e2[c] = (float)s;
            atomicMax(&g_cbmax_bits, __float_as_uint(mx));
            atomicMax(&g_scmax_bits, __float_as_uint(sa));
        }
    }
}

// ---------------- prep2: quantize codebook int8 pair-permuted ----------------
__global__ void vq_prep2_kernel(const float* __restrict__ cb) {
    float cbmax = __uint_as_float(g_cbmax_bits);
    float sc = (cbmax > 0.0f) ? 126.0f / cbmax : 1.0f;
    uint32_t* out8 = (uint32_t*)g_cb8;
    int base = blockIdx.x * 256 + threadIdx.x;
    #pragma unroll
    for (int i = 0; i < 8; i++) {
        int w = base + i * 8192;
        int n = w >> 6, m = w & 63;
        int G = m >> 3, p = m & 7;
        int o = (p & 1) ? ((p >> 1) + 4) : (p >> 1);
        int k0 = G * 32 + o * 4;
        const float* src = cb + (size_t)n * DIM + k0;
        int b0 = quant8(src[0], sc), b1 = quant8(src[1], sc);
        int b2 = quant8(src[2], sc), b3 = quant8(src[3], sc);
        out8[w] = (uint32_t)(b0 & 0xff) | ((uint32_t)(b1 & 0xff) << 8)
                | ((uint32_t)(b2 & 0xff) << 16) | ((uint32_t)(b3 & 0xff) << 24);
    }
}

// ---------------- main: 1024 threads, 32 warps (4 M x 8 N) ----------------
__global__ __launch_bounds__(BLOCK) void vq_main_kernel(
    const float* __restrict__ z,
    const float* __restrict__ cb,
    float* __restrict__ out)
{
    extern __shared__ char smem[];
    const uint32_t sbu = smem_u32(smem);
    uint32_t* a8w   = (uint32_t*)(smem + SA8);
    uint32_t* qd    = (uint32_t*)(smem + SQD);
    float*    e2s   = (float*)(smem + SE2);
    float*    z2s   = (float*)(smem + SZ2);
    float*    invs  = (float*)(smem + SINV);
    int*      wqs   = (int*)(smem + SWQ);
    float*    szs   = (float*)(smem + SSZ);
    int*      ccnt  = (int*)(smem + SCN);
    int*      minqs = (int*)(smem + SMINQ);
    int*      bi_s  = (int*)(smem + SBI);
    int*      clist = (int*)(smem + SCL);

    const int tid  = threadIdx.x;
    const int wid  = tid >> 5;
    const int lane = tid & 31;
    const int q    = lane & 3;
    const int lq   = lane >> 2;
    const int m0   = blockIdx.x * MCTA;
    const int mw   = (wid & 3) * 16;     // warp M base (4 warps in M)
    const int nw   = (wid >> 2) * 16;    // warp N base within 128-ntile (8 warps in N)

    const float cbmax = __uint_as_float(g_cbmax_bits);
    const float scmax = __uint_as_float(g_scmax_bits);
    const float sc  = (cbmax > 0.0f) ? 126.0f / cbmax : 1.0f;
    const float dcq = 0.5f / sc;

    // ---- e2 table, init ----
    e2s[tid] = g_e2[tid];
    if (tid < MCTA) ccnt[tid] = 0;

    // ---- per-row stats (fp64 z2, sum|z|, max|z|): warp w owns rows 2w..2w+1 ----
    #pragma unroll
    for (int rr = 0; rr < 2; rr++) {
        int r = wid * 2 + rr;
        const float* zr = z + (size_t)(m0 + r) * DIM;
        double s = 0.0; float sa = 0.0f, mx = 0.0f;
        #pragma unroll
        for (int i = 0; i < 8; i++) {
            float v = zr[lane + 32 * i];
            s += (double)v * (double)v;
            sa += fabsf(v);
            mx = fmaxf(mx, fabsf(v));
        }
        #pragma unroll
        for (int o = 16; o; o >>= 1) {
            s  += __shfl_xor_sync(0xffffffffu, s, o);
            sa += __shfl_xor_sync(0xffffffffu, sa, o);
            mx = fmaxf(mx, __shfl_xor_sync(0xffffffffu, mx, o));
        }
        if (lane == 0) {
            float sz = (mx > 0.0f) ? 126.0f / mx : 1.0f;
            float dzr = 0.5f / sz;
            float E = dzr * scmax + dcq * sa + 256.0f * dzr * dcq;  // hard dot-err bound
            z2s[r]  = (float)s;
            szs[r]  = sz;
            invs[r] = 1.0f / (sz * sc);
            wqs[r]  = (int)(4.0f * E * 32768.0f) + 8;
        }
    }
    __syncthreads();

    // ---- stage A int8 pair-permuted (4096 words) ----
    #pragma unroll
    for (int i = 0; i < 4; i++) {
        int s = i * BLOCK + tid;
        int row = s >> 6, ow = s & 63;
        int G = ow >> 3, o = ow & 7;
        int k0 = G * 32 + o * 4;
        float sz = szs[row];
        const float* src = z + (size_t)(m0 + row) * DIM + k0;
        int b0 = quant8(src[0], sz), b1 = quant8(src[1], sz);
        int b2 = quant8(src[2], sz), b3 = quant8(src[3], sz);
        int dw = (o < 4) ? 2 * o : 2 * (o - 4) + 1;
        a8w[row * A8_STRIDE_W + G * 8 + dw] =
            (uint32_t)(b0 & 0xff) | ((uint32_t)(b1 & 0xff) << 8)
          | ((uint32_t)(b2 & 0xff) << 16) | ((uint32_t)(b3 & 0xff) << 24);
    }
    __syncthreads();

    // ---- B chunk loader: chunk c -> ntile c>>2, k64-chunk c&3, buffer c&3 ----
    auto load_chunk = [&](int c) {
        if (tid < 512) {
            int nt = c >> 2, kc = c & 3;
            const char* src0 = (const char*)g_cb8 + (size_t)nt * 128 * 256 + kc * 64;
            uint32_t bbase = sbu + SBB + (c & 3) * BBUF_BYTES;
            int n = tid >> 2, seg = tid & 3;
            CP16(bbase + n * 80 + seg * 16, src0 + (size_t)n * 256 + seg * 16);
        }
    };
    load_chunk(0); CP_COMMIT();
    load_chunk(1); CP_COMMIT();
    load_chunk(2); CP_COMMIT();

    int acc[2][4];
    #pragma unroll
    for (int j = 0; j < 2; j++)
        #pragma unroll
        for (int e = 0; e < 4; e++) acc[j][e] = 0;

    const int r0 = mw + lq;
    const float inv0 = invs[r0], inv1 = invs[r0 + 8];

    for (int c = 0; c < 32; c++) {
        const int nt = c >> 2, kc = c & 3;
        CP_WAIT2();           // chunk c resident (per-thread)
        __syncthreads();      // all threads' waits done; buffer (c-1)&3 free
        if (c + 3 < 32) load_chunk(c + 3);
        CP_COMMIT();          // uniform group cadence

        const uint32_t* Bw = (const uint32_t*)(smem + SBB + (c & 3) * BBUF_BYTES);
        #pragma unroll
        for (int g = 0; g < 2; g++) {
            const int aw = (kc * 2 + g) * 8 + 2 * q;
            uint2 A0 = *(const uint2*)(a8w + r0 * A8_STRIDE_W + aw);
            uint2 A1 = *(const uint2*)(a8w + (r0 + 8) * A8_STRIDE_W + aw);
            #pragma unroll
            for (int j = 0; j < 2; j++) {
                int nl = nw + 8 * j + lq;
                uint2 B0 = *(const uint2*)(Bw + nl * B_STRIDE_W + g * 8 + 2 * q);
                mma_s8(acc[j][0], acc[j][1], acc[j][2], acc[j][3],
                       A0.x, A1.x, A0.y, A1.y, B0.x, B0.y);
            }
        }

        if (kc == 3) {
            // q16 = round((e2 - 2*isum*inv) * 2^15)
            #pragma unroll
            for (int j = 0; j < 2; j++) {
                int col0 = nt * 128 + nw + 8 * j + 2 * q;
                float e20 = e2s[col0], e21 = e2s[col0 + 1];
                int wIdx = (col0 >> 1);
                #pragma unroll
                for (int h = 0; h < 2; h++) {
                    float inv = h ? inv1 : inv0;
                    float s0 = e20 - 2.0f * ((float)acc[j][h * 2 + 0] * inv);
                    float s1 = e21 - 2.0f * ((float)acc[j][h * 2 + 1] * inv);
                    int q0 = max(-32767, min(32767, __float2int_rn(s0 * 32768.0f)));
                    int q1 = max(-32767, min(32767, __float2int_rn(s1 * 32768.0f)));
                    qd[(r0 + 8 * h) * QD_STRIDE_W + wIdx] =
                        ((uint32_t)(q1 & 0xffff) << 16) | (uint32_t)(q0 & 0xffff);
                    acc[j][h * 2 + 0] = 0;
                    acc[j][h * 2 + 1] = 0;
                }
            }
        }
    }
    __syncthreads();

    // ---- per-row FINAL min + capture (warp w owns rows 2w..2w+1, uint4 loads) ----
    for (int rr = 0; rr < 2; rr++) {
        int r = wid * 2 + rr;
        const uint4* row4 = (const uint4*)(qd + r * QD_STRIDE_W);
        uint4 v[4];
        int mn = 0x7fffffff;
        #pragma unroll
        for (int i = 0; i < 4; i++) {
            v[i] = row4[lane + 32 * i];
            const uint32_t* vw = (const uint32_t*)&v[i];
            #pragma unroll
            for (int w = 0; w < 4; w++) {
                int a = (int)(short)(vw[w] & 0xffff);
                int b = (int)(short)(vw[w] >> 16);
                mn = min(mn, min(a, b));
            }
        }
        #pragma unroll
        for (int o = 16; o; o >>= 1) mn = min(mn, __shfl_xor_sync(0xffffffffu, mn, o));
        int thr = mn + wqs[r];
        #pragma unroll
        for (int i = 0; i < 4; i++) {
            const uint32_t* vw = (const uint32_t*)&v[i];
            #pragma unroll
            for (int w = 0; w < 4; w++) {
                int a = (int)(short)(vw[w] & 0xffff);
                int b = (int)(short)(vw[w] >> 16);
                int colw = (lane + 32 * i) * 4 + w;
                if (a <= thr) {
                    int p = atomicAdd(&ccnt[r], 1);
                    if (p < CCAP) clist[r * CCAP + p] = 2 * colw;
                }
                if (b <= thr) {
                    int p = atomicAdd(&ccnt[r], 1);
                    if (p < CCAP) clist[r * CCAP + p] = 2 * colw + 1;
                }
            }
        }
        if (lane == 0) minqs[r] = mn;
    }
    __syncthreads();

    // ---- warp-parallel exact fp32 rescue (warp w owns rows 2w..2w+1) ----
    for (int rr = 0; rr < 2; rr++) {
        int r = wid * 2 + rr;
        const float z2f = z2s[r];
        const float* zr = z + (size_t)(m0 + r) * DIM;
        float zv[8];
        #pragma unroll
        for (int i = 0; i < 8; i++) zv[i] = zr[lane + 32 * i];

        float best = CUDART_INF_F; int bi = 0x7fffffff;
        int cnt = ccnt[r];
        int n_check = (cnt <= CCAP) ? cnt : NE;
        for (int p = 0; p < n_check; p++) {
            int cidx = (cnt <= CCAP) ? clist[r * CCAP + p] : p;
            const float* cr = cb + (size_t)cidx * DIM;
            float part = 0.0f;
            #pragma unroll
            for (int i = 0; i < 8; i++)
                part = fmaf(zv[i], __ldg(cr + lane + 32 * i), part);
            #pragma unroll
            for (int o = 16; o; o >>= 1)
                part += __shfl_xor_sync(0xffffffffu, part, o);
            float dd = (z2f - 2.0f * part) + e2s[cidx];
            if (dd < best || (dd == best && cidx < bi)) { best = dd; bi = cidx; }
        }
        if (lane == 0) bi_s[r] = bi;
    }
    __syncthreads();

    // ---- epilogue: z_q_st (exact ST rounding), indices, loss ----
    const int rg  = tid >> 8;           // 0..3: row group of 16
    const int col = tid & 255;
    float lacc = 0.0f;
    #pragma unroll 4
    for (int it = 0; it < 16; it++) {
        int row = rg * 16 + it;
        float zv = z[(size_t)(m0 + row) * DIM + col];
        float e  = __ldg(cb + (size_t)bi_s[row] * DIM + col);
        float dq = e - zv;                  // fl(z_q - z)
        float o  = zv + dq;                 // fl(z + fl(z_q - z))
        out[(size_t)(m0 + row) * DIM + col] = o;
        lacc = fmaf(dq, dq, lacc);
    }
    if (tid < MCTA)
        out[(size_t)NT * DIM + 1 + m0 + tid] = (float)bi_s[tid];

    double* red = (double*)(smem + SRED);
    red[tid] = (double)lacc;
    __syncthreads();
    #pragma unroll
    for (int s = 512; s > 0; s >>= 1) {
        if (tid < s) red[tid] += red[tid + s];
        __syncthreads();
    }
    if (tid == 0) atomicAdd(&g_loss_acc, red[0]);
}

__global__ void vq_loss_kernel(float* __restrict__ out) {
    out[(size_t)NT * DIM] = (float)(1.25 * g_loss_acc / ((double)NT * (double)DIM));
}

// ---------------------------------------------------------------------------
extern "C" void kernel_launch(void* const* d_in, const int* in_sizes, int n_in,
                              void* d_out, int out_size) {
    const float *z, *cb;
    if (in_sizes[0] == NT * DIM) { z = (const float*)d_in[0]; cb = (const float*)d_in[1]; }
    else                         { z = (const float*)d_in[1]; cb = (const float*)d_in[0]; }
    float* out = (float*)d_out;

    cudaFuncSetAttribute(vq_main_kernel,
                         cudaFuncAttributeMaxDynamicSharedMemorySize, SMEM_TOTAL);

    vq_prep1_kernel<<<32, 256>>>(cb);
    vq_prep2_kernel<<<32, 256>>>(cb);
    vq_main_kernel<<<NT / MCTA, BLOCK, SMEM_TOTAL>>>(z, cb, out);
    vq_loss_kernel<<<1, 1>>>(out);
}